// round 16
// baseline (speedup 1.0000x reference)
#include <cuda_runtime.h>
#include <cuda_bf16.h>
#include <cstdint>
#include <cstddef>

#define B_  8192
#define F_  32
#define D_  128
#define H_  128
#define FD_ 4096
#define PADR 65
#define MPITCH 136   // bf16 pitch for 128-wide mma tiles (conflict-free)
#define PA 72        // bf16 pitch for 64-wide streaming-gemm tiles

// ---------------- scratch (device globals; no allocation) ----------------
__device__ float g_stacked[(size_t)B_ * FD_];
__device__ float g_t[(size_t)B_ * FD_];
__device__ float g_u1[F_ * H_];
__device__ float g_c1[F_ * H_];
__device__ float g_bgp[F_ * 2 * D_];
__device__ float g_bpp[2 * FD_];
__device__ float g_psum[(size_t)B_ * 64];
__device__ float g_psq [(size_t)B_ * 64];
__device__ __nv_bfloat16 g_WgpT_hi[(size_t)F_ * 2 * D_ * H_];
__device__ __nv_bfloat16 g_WgpT_lo[(size_t)F_ * 2 * D_ * H_];
__device__ __nv_bfloat16 g_g_hi[(size_t)B_ * H_];
__device__ __nv_bfloat16 g_g_lo[(size_t)B_ * H_];
__device__ __nv_bfloat16 g_WT_hi[(size_t)2 * FD_ * H_];
__device__ __nv_bfloat16 g_WT_lo[(size_t)2 * FD_ * H_];
__device__ __nv_bfloat16 g_sW2_hi[(size_t)H_ * FD_];
__device__ __nv_bfloat16 g_sW2_lo[(size_t)H_ * FD_];
__device__ __nv_bfloat16 g_sW1T_hi[(size_t)H_ * FD_];
__device__ __nv_bfloat16 g_sW1T_lo[(size_t)H_ * FD_];

__device__ __forceinline__ float elu_f(float v) { return v > 0.f ? v : expm1f(v); }
__device__ __forceinline__ float sig_f(float v) { return 1.f / (1.f + __expf(-v)); }
__device__ __forceinline__ void split2(float v, __nv_bfloat16& h, __nv_bfloat16& l) {
    h = __float2bfloat16(v);
    l = __float2bfloat16(v - __bfloat162float(h));
}
__device__ __forceinline__ void splitpack2(float v0, float v1, uint32_t& hp, uint32_t& lp) {
    __nv_bfloat16 h0, l0, h1, l1;
    split2(v0, h0, l0); split2(v1, h1, l1);
    __nv_bfloat162 hh; hh.x = h0; hh.y = h1;
    __nv_bfloat162 ll; ll.x = l0; ll.y = l1;
    hp = *(uint32_t*)&hh; lp = *(uint32_t*)&ll;
}

__device__ __forceinline__ void mma16816(float* c, const uint32_t* a, const uint32_t* b) {
    asm volatile("mma.sync.aligned.m16n8k16.row.col.f32.bf16.bf16.f32 "
        "{%0,%1,%2,%3}, {%4,%5,%6,%7}, {%8,%9}, {%0,%1,%2,%3};"
        : "+f"(c[0]), "+f"(c[1]), "+f"(c[2]), "+f"(c[3])
        : "r"(a[0]), "r"(a[1]), "r"(a[2]), "r"(a[3]), "r"(b[0]), "r"(b[1]));
}
__device__ __forceinline__ void ldsm4(uint32_t& r0, uint32_t& r1, uint32_t& r2,
                                      uint32_t& r3, uint32_t addr) {
    asm volatile("ldmatrix.sync.aligned.m8n8.x4.shared.b16 {%0,%1,%2,%3}, [%4];"
        : "=r"(r0), "=r"(r1), "=r"(r2), "=r"(r3) : "r"(addr));
}
__device__ __forceinline__ uint32_t smem_u32(const void* p) {
    uint32_t a;
    asm("{ .reg .u64 t; cvta.to.shared.u64 t, %1; cvt.u32.u64 %0, t; }" : "=r"(a) : "l"(p));
    return a;
}

// ---------------- K0: fold rank-1 + weight products (grid F x 4) ----------
__global__ void k_pre(const float* __restrict__ Wp,  const float* __restrict__ bp,
                      const float* __restrict__ fW1, const float* __restrict__ fb1,
                      const float* __restrict__ fW2, const float* __restrict__ fb2,
                      const float* __restrict__ fWg, const float* __restrict__ fbg)
{
    __shared__ float sA[128 * PADR];
    __shared__ float sB[16 * 128];
    const int f = blockIdx.x, q = blockIdx.y, tid = threadIdx.x;
    const int mh = q >> 1, nh = q & 1;

    if (q == 0) {
        float acc = 0.f;
        for (int d = 0; d < 128; d++)
            acc += fb2[f * D_ + d] * fWg[((size_t)f * D_ + d) * 256 + tid];
        g_bgp[f * 256 + tid] = acc + fbg[f * 256 + tid];
    } else if (q == 1 && tid < 128) {
        float acc = 0.f;
        for (int d = 0; d < 128; d++)
            acc += Wp[f * D_ + d] * fW1[((size_t)f * D_ + d) * H_ + tid];
        g_u1[f * H_ + tid] = acc;
    } else if (q == 2 && tid < 128) {
        float acc = 0.f;
        for (int d = 0; d < 128; d++)
            acc += bp[f * D_ + d] * fW1[((size_t)f * D_ + d) * H_ + tid];
        g_c1[f * H_ + tid] = acc + fb1[f * H_ + tid];
    }

    for (int i = tid; i < 128 * 64; i += 256) {
        int m = i >> 7, d = i & 127;
        sA[d * PADR + m] = fW2[((size_t)f * H_ + mh * 64 + m) * D_ + d];
    }
    __syncthreads();

    const int tx = tid & 15, ty = tid >> 4;
    float acc[4][8] = {};
    for (int k0 = 0; k0 < 128; k0 += 16) {
        __syncthreads();
        {
            int kk = tid >> 4, nb = (tid & 15) * 8;
            const float* src = fWg + ((size_t)f * D_ + k0 + kk) * 256 + nh * 128 + nb;
            float4 v0 = *(const float4*)src;
            float4 v1 = *(const float4*)(src + 4);
            *(float4*)(sB + kk * 128 + nb)     = v0;
            *(float4*)(sB + kk * 128 + nb + 4) = v1;
        }
        __syncthreads();
#pragma unroll
        for (int k = 0; k < 16; k++) {
            float av[4], bv[8];
#pragma unroll
            for (int i = 0; i < 4; i++) av[i] = sA[(k0 + k) * PADR + 4 * tx + i];
#pragma unroll
            for (int j = 0; j < 8; j++) bv[j] = sB[k * 128 + 8 * ty + j];
#pragma unroll
            for (int i = 0; i < 4; i++)
#pragma unroll
                for (int j = 0; j < 8; j++) acc[i][j] += av[i] * bv[j];
        }
    }
#pragma unroll
    for (int i = 0; i < 4; i++)
#pragma unroll
        for (int j = 0; j < 8; j++) {
            int m = mh * 64 + 4 * tx + i;
            int e = nh * 128 + 8 * ty + j;
            int p = (e < 128) ? (2 * e) : (2 * (e - 128) + 1);
            __nv_bfloat16 h, l; split2(acc[i][j], h, l);
            size_t idx = ((size_t)f * 256 + p) * H_ + m;
            g_WgpT_hi[idx] = h; g_WgpT_lo[idx] = l;
        }
}

// ---------------- K0b: pre-convert sW2 / sW1^T to bf16 hi/lo --------------
__global__ void k_conv(const float* __restrict__ sW1, const float* __restrict__ sW2)
{
    int i = blockIdx.x * 256 + threadIdx.x;
    {
        float v = sW2[i];
        __nv_bfloat16 h, l; split2(v, h, l);
        g_sW2_hi[i] = h; g_sW2_lo[i] = l;
    }
    {
        int hq = i >> 12, k = i & 4095;
        float v = sW1[(size_t)k * H_ + hq];
        __nv_bfloat16 h, l; split2(v, h, l);
        g_sW1T_hi[i] = h; g_sW1T_lo[i] = l;
    }
}

// ---------------- K1: per-feature GRN via mma (ldmatrix) + LN -------------
__global__ void __launch_bounds__(512, 1) k_grn2_mma(
    const float* __restrict__ x,  const float* __restrict__ Wp,
    const float* __restrict__ bp, const float* __restrict__ fg,
    const float* __restrict__ fbe)
{
    extern __shared__ char smg[];
    __nv_bfloat16* sAh = (__nv_bfloat16*)smg;
    __nv_bfloat16* sAl = sAh + 128 * MPITCH;
    __nv_bfloat16* sBh = sAl + 128 * MPITCH;
    __nv_bfloat16* sBl = sBh + 256 * MPITCH;
    float* s_val = (float*)smg;

    const int f = blockIdx.y, b0 = blockIdx.x * 128, tid = threadIdx.x;
    const int wid = tid >> 5, lane = tid & 31;

    {
        int r = tid >> 2, d0 = (tid & 3) * 32;
        float xv = x[(size_t)(b0 + r) * F_ + f];
        const float* u1 = g_u1 + f * H_ + d0;
        const float* c1 = g_c1 + f * H_ + d0;
#pragma unroll
        for (int j = 0; j < 16; j++) {
            float v0 = elu_f(xv * u1[2*j]   + c1[2*j]);
            float v1 = elu_f(xv * u1[2*j+1] + c1[2*j+1]);
            uint32_t hp, lp;
            splitpack2(v0, v1, hp, lp);
            *(uint32_t*)(sAh + r * MPITCH + d0 + 2*j) = hp;
            *(uint32_t*)(sAl + r * MPITCH + d0 + 2*j) = lp;
        }
    }
    {
        const uint4* srcH = (const uint4*)(g_WgpT_hi + (size_t)f * 256 * H_);
        const uint4* srcL = (const uint4*)(g_WgpT_lo + (size_t)f * 256 * H_);
        for (int i = tid; i < 256 * 16; i += 512) {
            int r = i >> 4, c = i & 15;
            *(uint4*)(sBh + r * MPITCH + c * 8) = srcH[r * 16 + c];
            *(uint4*)(sBl + r * MPITCH + c * 8) = srcL[r * 16 + c];
        }
    }
    __syncthreads();

    const int wm = (wid >> 3) * 64, wn = (wid & 7) * 32;
    const int lr = lane >> 2, lc = (lane & 3) * 2;
    const int g8 = lane >> 3, lr8 = lane & 7;
    const int arow = (g8 & 1) * 8 + lr8, acol = (g8 >> 1) * 8;
    const int brow = (g8 >> 1) * 8 + lr8, bcol = (g8 & 1) * 8;
    const uint32_t sbase = smem_u32(smg);

    float acc[4][4][4];
#pragma unroll
    for (int mt = 0; mt < 4; mt++)
#pragma unroll
        for (int nt = 0; nt < 4; nt++)
#pragma unroll
            for (int q = 0; q < 4; q++) acc[mt][nt][q] = 0.f;

#pragma unroll
    for (int pass = 0; pass < 3; pass++) {
        uint32_t uAr = sbase + ((pass == 1) ? 128u * MPITCH * 2u : 0u)
                     + (uint32_t)((wm + arow) * MPITCH + acol) * 2u;
        uint32_t uBr = sbase + 256u * MPITCH * 2u + ((pass == 2) ? 256u * MPITCH * 2u : 0u)
                     + (uint32_t)((wn + brow) * MPITCH + bcol) * 2u;
#pragma unroll
        for (int ks = 0; ks < 8; ks++) {
            const uint32_t k0b = ks * 32;
            uint32_t a[4][4], b[4][2];
#pragma unroll
            for (int mt = 0; mt < 4; mt++)
                ldsm4(a[mt][0], a[mt][1], a[mt][2], a[mt][3],
                      uAr + mt * (16 * MPITCH * 2) + k0b);
#pragma unroll
            for (int p = 0; p < 2; p++)
                ldsm4(b[2*p][0], b[2*p][1], b[2*p+1][0], b[2*p+1][1],
                      uBr + p * (16 * MPITCH * 2) + k0b);
#pragma unroll
            for (int mt = 0; mt < 4; mt++)
#pragma unroll
                for (int nt = 0; nt < 4; nt++)
                    mma16816(acc[mt][nt], a[mt], b[nt]);
        }
    }
    __syncthreads();

    const float* bgp = g_bgp + f * 256;
#pragma unroll
    for (int mt = 0; mt < 4; mt++) {
        int r0 = wm + mt * 16 + lr;
        float xv0 = x[(size_t)(b0 + r0) * F_ + f];
        float xv1 = x[(size_t)(b0 + r0 + 8) * F_ + f];
#pragma unroll
        for (int nt = 0; nt < 4; nt++) {
            int cc = wn + nt * 8 + lc;
            int j = cc >> 1;
            float ba = bgp[j], bs = bgp[128 + j];
            float wpj = Wp[f * D_ + j], bpj = bp[f * D_ + j];
            float a0 = acc[mt][nt][0] + ba, s0 = acc[mt][nt][1] + bs;
            s_val[r0 * 132 + j] = (xv0 * wpj + bpj) + a0 * sig_f(s0);
            float a1 = acc[mt][nt][2] + ba, s1 = acc[mt][nt][3] + bs;
            s_val[(r0 + 8) * 132 + j] = (xv1 * wpj + bpj) + a1 * sig_f(s1);
        }
    }
    __syncthreads();

    for (int rr = wid; rr < 128; rr += 16) {
        float v[4]; float sum = 0.f, sq = 0.f;
#pragma unroll
        for (int i = 0; i < 4; i++) {
            float val = s_val[rr * 132 + lane + 32 * i];
            v[i] = val; sum += val; sq += val * val;
        }
#pragma unroll
        for (int o = 16; o; o >>= 1) {
            sum += __shfl_xor_sync(0xffffffffu, sum, o);
            sq  += __shfl_xor_sync(0xffffffffu, sq,  o);
        }
        float mu  = sum * (1.f / 128.f);
        float var = sq  * (1.f / 128.f) - mu * mu;
        float rs  = rsqrtf(var + 1e-5f);
#pragma unroll
        for (int i = 0; i < 4; i++) {
            int d = lane + 32 * i;
            float o = (v[i] - mu) * rs * fg[f * D_ + d] + fbe[f * D_ + d];
            g_stacked[((size_t)(b0 + rr) * F_ + f) * D_ + d] = o;
        }
    }
}

// ---------------- K3: W'' = (sW2@sWg)^T via mma, streaming K=4096 ---------
__global__ void __launch_bounds__(256, 1) k_wpp_mma(const float* __restrict__ sWg,
                                                    const float* __restrict__ sb2,
                                                    const float* __restrict__ sbg)
{
    extern __shared__ char sm4[];
    const int ASZ = 64 * PA * 2, BSZ = 128 * PA * 2;
    __nv_bfloat16* Ahs[2] = {(__nv_bfloat16*)sm4, (__nv_bfloat16*)(sm4 + ASZ)};
    __nv_bfloat16* Als[2] = {(__nv_bfloat16*)(sm4 + 2*ASZ), (__nv_bfloat16*)(sm4 + 3*ASZ)};
    __nv_bfloat16* Bhs[2] = {(__nv_bfloat16*)(sm4 + 4*ASZ), (__nv_bfloat16*)(sm4 + 4*ASZ + BSZ)};
    __nv_bfloat16* Bls[2] = {(__nv_bfloat16*)(sm4 + 4*ASZ + 2*BSZ), (__nv_bfloat16*)(sm4 + 4*ASZ + 3*BSZ)};
    float* part = (float*)(sm4 + 4*ASZ + 4*BSZ);

    const int c0 = blockIdx.x * 64;
    const int tid = threadIdx.x, wid = tid >> 5, lane = tid & 31;
    const int kr = tid >> 2, cb = tid & 3;
    const int mr = tid >> 1, kh = (tid & 1) * 32;

    float areg[16];
    uint4 bregH[4], bregL[4];
    float baccp[16];
#pragma unroll
    for (int i = 0; i < 16; i++) baccp[i] = 0.f;

    auto ldchunk = [&](int ch) {
        const float* asrc = sWg + (size_t)(ch * 64 + kr) * (2 * FD_) + c0 + cb * 16;
#pragma unroll
        for (int j = 0; j < 4; j++) {
            float4 v = *(const float4*)(asrc + 4 * j);
            areg[4*j+0] = v.x; areg[4*j+1] = v.y; areg[4*j+2] = v.z; areg[4*j+3] = v.w;
        }
        const uint4* bh = (const uint4*)(g_sW2_hi + (size_t)mr * FD_ + ch * 64 + kh);
        const uint4* bl = (const uint4*)(g_sW2_lo + (size_t)mr * FD_ + ch * 64 + kh);
#pragma unroll
        for (int j = 0; j < 4; j++) { bregH[j] = bh[j]; bregL[j] = bl[j]; }
        float sv = sb2[ch * 64 + kr];
#pragma unroll
        for (int i = 0; i < 16; i++) baccp[i] += sv * areg[i];
    };
    auto stchunk = [&](int buf) {
        __nv_bfloat16* ah = Ahs[buf]; __nv_bfloat16* al = Als[buf];
#pragma unroll
        for (int i = 0; i < 16; i++) {
            int cl = cb * 16 + i;
            __nv_bfloat16 h, l; split2(areg[i], h, l);
            ah[cl * PA + kr] = h;
            al[cl * PA + kr] = l;
        }
        uint4* bh = (uint4*)(Bhs[buf] + mr * PA + kh);
        uint4* bl = (uint4*)(Bls[buf] + mr * PA + kh);
#pragma unroll
        for (int j = 0; j < 4; j++) { bh[j] = bregH[j]; bl[j] = bregL[j]; }
    };

    const int wc = (wid & 3) * 16, wm = (wid >> 2) * 64;
    const int lr = lane >> 2, lc = (lane & 3) * 2;
    float acc[8][4];
#pragma unroll
    for (int i = 0; i < 8; i++)
#pragma unroll
        for (int j = 0; j < 4; j++) acc[i][j] = 0.f;

    auto compute = [&](int buf) {
#pragma unroll
        for (int pass = 0; pass < 3; pass++) {
            const __nv_bfloat16* A = (pass == 1) ? Als[buf] : Ahs[buf];
            const __nv_bfloat16* B = (pass == 2) ? Bls[buf] : Bhs[buf];
#pragma unroll
            for (int ks = 0; ks < 4; ks++) {
                int k0 = ks * 16;
                uint32_t a[4];
                const __nv_bfloat16* ab = A + (wc + lr) * PA + k0 + lc;
                a[0] = *(const uint32_t*)ab;
                a[1] = *(const uint32_t*)(ab + 8 * PA);
                a[2] = *(const uint32_t*)(ab + 8);
                a[3] = *(const uint32_t*)(ab + 8 * PA + 8);
#pragma unroll
                for (int nt = 0; nt < 8; nt++) {
                    const __nv_bfloat16* bb = B + (wm + nt * 8 + lr) * PA + k0 + lc;
                    uint32_t b[2] = {*(const uint32_t*)bb, *(const uint32_t*)(bb + 8)};
                    mma16816(acc[nt], a, b);
                }
            }
        }
    };

    ldchunk(0); stchunk(0); __syncthreads();
    for (int ch = 0; ch < 64; ch++) {
        int cur = ch & 1;
        if (ch < 63) ldchunk(ch + 1);
        compute(cur);
        if (ch < 63) { stchunk(cur ^ 1); __syncthreads(); }
    }

#pragma unroll
    for (int nt = 0; nt < 8; nt++) {
        int m = wm + nt * 8 + lc;
#pragma unroll
        for (int half = 0; half < 2; half++) {
            int c = c0 + wc + lr + half * 8;
            int p = (c < FD_) ? (2 * c) : (2 * (c - FD_) + 1);
            uint32_t hp, lp;
            splitpack2(acc[nt][half * 2], acc[nt][half * 2 + 1], hp, lp);
            *(uint32_t*)(g_WT_hi + (size_t)p * H_ + m) = hp;
            *(uint32_t*)(g_WT_lo + (size_t)p * H_ + m) = lp;
        }
    }

    __syncthreads();
#pragma unroll
    for (int i = 0; i < 16; i++) part[tid * 16 + i] = baccp[i];
    __syncthreads();
    if (tid < 64) {
        int cb2 = tid >> 4, ii = tid & 15;
        float s = 0.f;
        for (int j = 0; j < 64; j++) s += part[(j * 4 + cb2) * 16 + ii];
        int c = c0 + tid;
        int p = (c < FD_) ? (2 * c) : (2 * (c - FD_) + 1);
        g_bpp[p] = s + sbg[c];
    }
}

// ---------------- K2: g = elu(flat @ sW1 + sb1) via mma -------------------
__global__ void __launch_bounds__(256, 1) k_sel1_mma(const float* __restrict__ sb1)
{
    extern __shared__ char sm5[];
    const int ASZ = 64 * PA * 2, BSZ = 128 * PA * 2;
    __nv_bfloat16* Ahs[2] = {(__nv_bfloat16*)sm5, (__nv_bfloat16*)(sm5 + ASZ)};
    __nv_bfloat16* Als[2] = {(__nv_bfloat16*)(sm5 + 2*ASZ), (__nv_bfloat16*)(sm5 + 3*ASZ)};
    __nv_bfloat16* Bhs[2] = {(__nv_bfloat16*)(sm5 + 4*ASZ), (__nv_bfloat16*)(sm5 + 4*ASZ + BSZ)};
    __nv_bfloat16* Bls[2] = {(__nv_bfloat16*)(sm5 + 4*ASZ + 2*BSZ), (__nv_bfloat16*)(sm5 + 4*ASZ + 3*BSZ)};

    const int b0 = blockIdx.x * 64;
    const int tid = threadIdx.x, wid = tid >> 5, lane = tid & 31;
    const int rr = tid >> 2, kq = (tid & 3) * 16;
    const int hr = tid >> 1, kh = (tid & 1) * 32;

    float areg[16];
    uint4 bregH[4], bregL[4];

    auto ldchunk = [&](int ch) {
        const float* asrc = g_stacked + (size_t)(b0 + rr) * FD_ + ch * 64 + kq;
#pragma unroll
        for (int j = 0; j < 4; j++) {
            float4 v = *(const float4*)(asrc + 4 * j);
            areg[4*j+0] = v.x; areg[4*j+1] = v.y; areg[4*j+2] = v.z; areg[4*j+3] = v.w;
        }
        const uint4* bh = (const uint4*)(g_sW1T_hi + (size_t)hr * FD_ + ch * 64 + kh);
        const uint4* bl = (const uint4*)(g_sW1T_lo + (size_t)hr * FD_ + ch * 64 + kh);
#pragma unroll
        for (int j = 0; j < 4; j++) { bregH[j] = bh[j]; bregL[j] = bl[j]; }
    };
    auto stchunk = [&](int buf) {
        __nv_bfloat16* ah = Ahs[buf]; __nv_bfloat16* al = Als[buf];
#pragma unroll
        for (int j = 0; j < 8; j++) {
            uint32_t hp, lp;
            splitpack2(areg[2*j], areg[2*j + 1], hp, lp);
            *(uint32_t*)(ah + rr * PA + kq + 2*j) = hp;
            *(uint32_t*)(al + rr * PA + kq + 2*j) = lp;
        }
        uint4* bh = (uint4*)(Bhs[buf] + hr * PA + kh);
        uint4* bl = (uint4*)(Bls[buf] + hr * PA + kh);
#pragma unroll
        for (int j = 0; j < 4; j++) { bh[j] = bregH[j]; bl[j] = bregL[j]; }
    };

    const int wc = (wid & 3) * 16, wm = (wid >> 2) * 64;
    const int lr = lane >> 2, lc = (lane & 3) * 2;
    float acc[8][4];
#pragma unroll
    for (int i = 0; i < 8; i++)
#pragma unroll
        for (int j = 0; j < 4; j++) acc[i][j] = 0.f;

    auto compute = [&](int buf) {
#pragma unroll
        for (int pass = 0; pass < 3; pass++) {
            const __nv_bfloat16* A = (pass == 1) ? Als[buf] : Ahs[buf];
            const __nv_bfloat16* B = (pass == 2) ? Bls[buf] : Bhs[buf];
#pragma unroll
            for (int ks = 0; ks < 4; ks++) {
                int k0 = ks * 16;
                uint32_t a[4];
                const __nv_bfloat16* ab = A + (wc + lr) * PA + k0 + lc;
                a[0] = *(const uint32_t*)ab;
                a[1] = *(const uint32_t*)(ab + 8 * PA);
                a[2] = *(const uint32_t*)(ab + 8);
                a[3] = *(const uint32_t*)(ab + 8 * PA + 8);
#pragma unroll
                for (int nt = 0; nt < 8; nt++) {
                    const __nv_bfloat16* bb = B + (wm + nt * 8 + lr) * PA + k0 + lc;
                    uint32_t b[2] = {*(const uint32_t*)bb, *(const uint32_t*)(bb + 8)};
                    mma16816(acc[nt], a, b);
                }
            }
        }
    };

    ldchunk(0); stchunk(0); __syncthreads();
    for (int ch = 0; ch < 64; ch++) {
        int cur = ch & 1;
        if (ch < 63) ldchunk(ch + 1);
        compute(cur);
        if (ch < 63) { stchunk(cur ^ 1); __syncthreads(); }
    }

#pragma unroll
    for (int nt = 0; nt < 8; nt++) {
        int h = wm + nt * 8 + lc;
        float bb0 = sb1[h], bb1 = sb1[h + 1];
#pragma unroll
        for (int half = 0; half < 2; half++) {
            int row = b0 + wc + lr + half * 8;
            float v0 = elu_f(acc[nt][half * 2]     + bb0);
            float v1 = elu_f(acc[nt][half * 2 + 1] + bb1);
            uint32_t hp, lp;
            splitpack2(v0, v1, hp, lp);
            *(uint32_t*)(g_g_hi + (size_t)row * H_ + h) = hp;
            *(uint32_t*)(g_g_lo + (size_t)row * H_ + h) = lp;
        }
    }
}

// ---------------- K4: gate mma (ldmatrix), emits LN partials --------------
__global__ void __launch_bounds__(512, 1) k_gate_mma()
{
    extern __shared__ __nv_bfloat16 smb[];
    __nv_bfloat16* sAh = smb;
    __nv_bfloat16* sAl = sAh + 128 * MPITCH;
    __nv_bfloat16* sBh = sAl + 128 * MPITCH;
    __nv_bfloat16* sBl = sBh + 128 * MPITCH;
    __shared__ float s_lns[128][4];
    __shared__ float s_lnq[128][4];

    const int m0 = blockIdx.x * 128;
    const int n0 = blockIdx.y * 128;
    const int tid = threadIdx.x;
    const int wid = tid >> 5, lane = tid & 31;

    for (int i = tid; i < 2048; i += 512) {
        int r = i >> 4, c = i & 15;
        *(uint4*)(sAh + r * MPITCH + c * 8) = *((const uint4*)(g_g_hi  + (size_t)(m0 + r) * H_) + c);
        *(uint4*)(sAl + r * MPITCH + c * 8) = *((const uint4*)(g_g_lo  + (size_t)(m0 + r) * H_) + c);
        *(uint4*)(sBh + r * MPITCH + c * 8) = *((const uint4*)(g_WT_hi + (size_t)(n0 + r) * H_) + c);
        *(uint4*)(sBl + r * MPITCH + c * 8) = *((const uint4*)(g_WT_lo + (size_t)(n0 + r) * H_) + c);
    }
    __syncthreads();

    const int wm = (wid & 3) * 32, wn = (wid >> 2) * 32;
    const int lr = lane >> 2, lc = (lane & 3) * 2;
    const int g8 = lane >> 3, lr8 = lane & 7;
    const int arow = (g8 & 1) * 8 + lr8, acol = (g8 >> 1) * 8;
    const int brow = (g8 >> 1) * 8 + lr8, bcol = (g8 & 1) * 8;
    const uint32_t sbase = smem_u32(smb);
    float acc[2][4][4] = {};

#pragma unroll
    for (int pass = 0; pass < 3; pass++) {
        uint32_t uAr = sbase + ((pass == 1) ? 128u * MPITCH * 2u : 0u)
                     + (uint32_t)((wm + arow) * MPITCH + acol) * 2u;
        uint32_t uBr = sbase + 256u * MPITCH * 2u + ((pass == 2) ? 128u * MPITCH * 2u : 0u)
                     + (uint32_t)((wn + brow) * MPITCH + bcol) * 2u;
#pragma unroll
        for (int ks = 0; ks < 8; ks++) {
            const uint32_t k0b = ks * 32;
            uint32_t a[2][4], b[4][2];
#pragma unroll
            for (int mt = 0; mt < 2; mt++)
                ldsm4(a[mt][0], a[mt][1], a[mt][2], a[mt][3],
                      uAr + mt * (16 * MPITCH * 2) + k0b);
#pragma unroll
            for (int p = 0; p < 2; p++)
                ldsm4(b[2*p][0], b[2*p][1], b[2*p+1][0], b[2*p+1][1],
                      uBr + p * (16 * MPITCH * 2) + k0b);
#pragma unroll
            for (int mt = 0; mt < 2; mt++)
#pragma unroll
                for (int nt = 0; nt < 4; nt++)
                    mma16816(acc[mt][nt], a[mt], b[nt]);
        }
    }

    float psum[4], psq[4];
#pragma unroll
    for (int i = 0; i < 4; i++) { psum[i] = 0.f; psq[i] = 0.f; }

#pragma unroll
    for (int mt = 0; mt < 2; mt++) {
        int r0 = m0 + wm + mt * 16 + lr;
#pragma unroll
        for (int nt = 0; nt < 4; nt++) {
            int cc = n0 + wn + nt * 8 + lc;
            int j = cc >> 1;
            float ba = g_bpp[cc], bs = g_bpp[cc + 1];
            float a0 = acc[mt][nt][0] + ba, s0 = acc[mt][nt][1] + bs;
            float t0 = g_stacked[(size_t)r0 * FD_ + j] + a0 * sig_f(s0);
            g_t[(size_t)r0 * FD_ + j] = t0;
            psum[mt*2] += t0; psq[mt*2] += t0 * t0;
            float a1 = acc[mt][nt][2] + ba, s1 = acc[mt][nt][3] + bs;
            float t1 = g_stacked[(size_t)(r0 + 8) * FD_ + j] + a1 * sig_f(s1);
            g_t[(size_t)(r0 + 8) * FD_ + j] = t1;
            psum[mt*2+1] += t1; psq[mt*2+1] += t1 * t1;
        }
    }

#pragma unroll
    for (int o = 1; o < 4; o <<= 1) {
#pragma unroll
        for (int i = 0; i < 4; i++) {
            psum[i] += __shfl_xor_sync(0xffffffffu, psum[i], o);
            psq[i]  += __shfl_xor_sync(0xffffffffu, psq[i],  o);
        }
    }
    if ((lane & 3) == 0) {
#pragma unroll
        for (int mt = 0; mt < 2; mt++) {
#pragma unroll
            for (int half = 0; half < 2; half++) {
                int rl = wm + mt * 16 + lr + half * 8;
                s_lns[rl][wid >> 2] = psum[mt*2 + half];
                s_lnq[rl][wid >> 2] = psq[mt*2 + half];
            }
        }
    }
    __syncthreads();
    if (tid < 128) {
        float s = s_lns[tid][0] + s_lns[tid][1] + s_lns[tid][2] + s_lns[tid][3];
        float q = s_lnq[tid][0] + s_lnq[tid][1] + s_lnq[tid][2] + s_lnq[tid][3];
        g_psum[(size_t)(m0 + tid) * 64 + blockIdx.y] = s;
        g_psq [(size_t)(m0 + tid) * 64 + blockIdx.y] = q;
    }
}

// ---------------- K5: LN(4096) -> logits GEMM -> softmax -> select --------
__global__ void k_final(const float* __restrict__ sg, const float* __restrict__ sbe,
                        const float* __restrict__ Wh, const float* __restrict__ bh,
                        float* __restrict__ out)
{
    __shared__ float As[2][32 * PADR];
    __shared__ float Bs[2][32 * 32];
    __shared__ float smu[64], srs[64];
    __shared__ float L[64 * 33];
    const int m0  = blockIdx.x * 64;
    const int tid = threadIdx.x;
    const int w = tid >> 5, l = tid & 31;

    for (int rr = w; rr < 64; rr += 8) {
        size_t base = (size_t)(m0 + rr) * 64;
        float sum = g_psum[base + l] + g_psum[base + 32 + l];
        float sq  = g_psq [base + l] + g_psq [base + 32 + l];
#pragma unroll
        for (int o = 16; o; o >>= 1) {
            sum += __shfl_xor_sync(0xffffffffu, sum, o);
            sq  += __shfl_xor_sync(0xffffffffu, sq,  o);
        }
        if (l == 0) {
            float mu  = sum * (1.f / 4096.f);
            float var = sq  * (1.f / 4096.f) - mu * mu;
            smu[rr] = mu;
            srs[rr] = rsqrtf(var + 1e-5f);
        }
    }
    __syncthreads();

    const int tx = tid & 15, ty = tid >> 4;
    const int ar = tid >> 2, akq = (tid & 3) * 8;
    const int bkk = tid >> 3, bnb = (tid & 7) * 4;
    float areg[8], sgr[8], sber[8];
    float4 breg;
    float mu_r = 0.f, rs_r = 0.f;

    auto ldchunk = [&](int ch) {
        const float* src = g_t + (size_t)(m0 + ar) * FD_ + ch * 32 + akq;
        float4 v0 = *(const float4*)src;
        float4 v1 = *(const float4*)(src + 4);
        areg[0] = v0.x; areg[1] = v0.y; areg[2] = v0.z; areg[3] = v0.w;
        areg[4] = v1.x; areg[5] = v1.y; areg[6] = v1.z; areg[7] = v1.w;
        float4 s0 = *(const float4*)(sg  + ch * 32 + akq);
        float4 s1 = *(const float4*)(sg  + ch * 32 + akq + 4);
        float4 e0 = *(const float4*)(sbe + ch * 32 + akq);
        float4 e1 = *(const float4*)(sbe + ch * 32 + akq + 4);
        sgr[0]=s0.x; sgr[1]=s0.y; sgr[2]=s0.z; sgr[3]=s0.w;
        sgr[4]=s1.x; sgr[5]=s1.y; sgr[6]=s1.z; sgr[7]=s1.w;
        sber[0]=e0.x; sber[1]=e0.y; sber[2]=e0.z; sber[3]=e0.w;
        sber[4]=e1.x; sber[5]=e1.y; sber[6]=e1.z; sber[7]=e1.w;
        breg = *(const float4*)(Wh + (size_t)(ch * 32 + bkk) * F_ + bnb);
    };
    auto stchunk = [&](int buf) {
#pragma unroll
        for (int q = 0; q < 8; q++)
            As[buf][(akq + q) * PADR + ar] = (areg[q] - mu_r) * rs_r * sgr[q] + sber[q];
        *(float4*)(Bs[buf] + bkk * 32 + bnb) = breg;
    };

    mu_r = smu[ar]; rs_r = srs[ar];
    float acc[4][2] = {};

    ldchunk(0); stchunk(0); __syncthreads();
    for (int ch = 0; ch < 128; ch++) {
        int cur = ch & 1;
        if (ch < 127) ldchunk(ch + 1);
        {
            const float* Ac = As[cur];
            const float* Bc = Bs[cur];
#pragma unroll
            for (int k = 0; k < 32; k++) {
                float a0 = Ac[k * PADR + 4 * tx + 0];
                float a1 = Ac[k * PADR + 4 * tx + 1];
                float a2 = Ac[k * PADR + 4 * tx + 2];
                float a3 = Ac[k * PADR + 4 * tx + 3];
                float b0 = Bc[k * 32 + 2 * ty];
                float b1 = Bc[k * 32 + 2 * ty + 1];
                acc[0][0] += a0 * b0; acc[0][1] += a0 * b1;
                acc[1][0] += a1 * b0; acc[1][1] += a1 * b1;
                acc[2][0] += a2 * b0; acc[2][1] += a2 * b1;
                acc[3][0] += a3 * b0; acc[3][1] += a3 * b1;
            }
        }
        if (ch < 127) { stchunk(cur ^ 1); __syncthreads(); }
    }
    __syncthreads();
#pragma unroll
    for (int i = 0; i < 4; i++)
#pragma unroll
        for (int j = 0; j < 2; j++)
            L[(4 * tx + i) * 33 + 2 * ty + j] = acc[i][j] + bh[2 * ty + j];
    __syncthreads();

    for (int rr = w; rr < 64; rr += 8) {
        int b = m0 + rr;
        float logit = L[rr * 33 + l];
        float mx = logit;
#pragma unroll
        for (int o = 16; o; o >>= 1) mx = fmaxf(mx, __shfl_xor_sync(0xffffffffu, mx, o));
        float e = __expf(logit - mx);
        float s = e;
#pragma unroll
        for (int o = 16; o; o >>= 1) s += __shfl_xor_sync(0xffffffffu, s, o);
        float wt = e / s;
        out[(size_t)B_ * D_ + (size_t)b * F_ + l] = wt;

        float accd[4] = {0.f, 0.f, 0.f, 0.f};
        const float* srow = g_stacked + (size_t)b * FD_;
        for (int ff = 0; ff < 32; ff++) {
            float wf = __shfl_sync(0xffffffffu, wt, ff);
#pragma unroll
            for (int i = 0; i < 4; i++)
                accd[i] += srow[ff * 128 + l + 32 * i] * wf;
        }
#pragma unroll
        for (int i = 0; i < 4; i++)
            out[(size_t)b * D_ + l + 32 * i] = accd[i];
    }
}

// ---------------- launch (two-stream overlap, capture-safe fork) ----------
extern "C" void kernel_launch(void* const* d_in, const int* in_sizes, int n_in,
                              void* d_out, int out_size)
{
    const float* x   = (const float*)d_in[0];
    const float* Wp  = (const float*)d_in[1];
    const float* bp  = (const float*)d_in[2];
    const float* fW1 = (const float*)d_in[3];
    const float* fb1 = (const float*)d_in[4];
    const float* fW2 = (const float*)d_in[5];
    const float* fb2 = (const float*)d_in[6];
    const float* fWg = (const float*)d_in[7];
    const float* fbg = (const float*)d_in[8];
    const float* fg  = (const float*)d_in[9];
    const float* fbe = (const float*)d_in[10];
    const float* sW1 = (const float*)d_in[11];
    const float* sb1 = (const float*)d_in[12];
    const float* sW2 = (const float*)d_in[13];
    const float* sb2 = (const float*)d_in[14];
    const float* sWg = (const float*)d_in[15];
    const float* sbg = (const float*)d_in[16];
    const float* sg  = (const float*)d_in[17];
    const float* sbe = (const float*)d_in[18];
    const float* Wh  = (const float*)d_in[19];
    const float* bh  = (const float*)d_in[20];
    float* out = (float*)d_out;

    const int ASZ = 64 * PA * 2, BSZ = 128 * PA * 2;
    const int SMG   = (2 * 128 + 2 * 256) * MPITCH * (int)sizeof(__nv_bfloat16); // 208896
    const int SMEM4 = 4 * 128 * MPITCH * (int)sizeof(__nv_bfloat16);             // 139264
    const int SMW   = 4 * ASZ + 4 * BSZ + 256 * 16 * (int)sizeof(float);
    const int SMS   = 4 * ASZ + 4 * BSZ;

    static cudaStream_t s1 = nullptr;
    static cudaEvent_t evRoot = nullptr, evConv = nullptr, evWpp = nullptr;
    if (!s1) {
        cudaFuncSetAttribute(k_grn2_mma, cudaFuncAttributeMaxDynamicSharedMemorySize, SMG);
        cudaFuncSetAttribute(k_gate_mma, cudaFuncAttributeMaxDynamicSharedMemorySize, SMEM4);
        cudaFuncSetAttribute(k_wpp_mma,  cudaFuncAttributeMaxDynamicSharedMemorySize, SMW);
        cudaFuncSetAttribute(k_sel1_mma, cudaFuncAttributeMaxDynamicSharedMemorySize, SMS);
        cudaStreamCreateWithFlags(&s1, cudaStreamNonBlocking);
        cudaEventCreateWithFlags(&evRoot, cudaEventDisableTiming);
        cudaEventCreateWithFlags(&evConv, cudaEventDisableTiming);
        cudaEventCreateWithFlags(&evWpp,  cudaEventDisableTiming);
    }

    // fork: conv + wpp chain on s1 (hidden under pre/grn2)
    cudaEventRecord(evRoot, 0);
    cudaStreamWaitEvent(s1, evRoot, 0);
    k_conv<<<2048, 256, 0, s1>>>(sW1, sW2);
    cudaEventRecord(evConv, s1);
    k_wpp_mma<<<2 * FD_ / 64, 256, SMW, s1>>>(sWg, sb2, sbg);
    cudaEventRecord(evWpp, s1);

    // main chain
    k_pre<<<dim3(F_, 4), 256>>>(Wp, bp, fW1, fb1, fW2, fb2, fWg, fbg);
    k_grn2_mma<<<dim3(B_ / 128, F_), 512, SMG>>>(x, Wp, bp, fg, fbe);
    cudaStreamWaitEvent(0, evConv, 0);
    k_sel1_mma<<<B_ / 64, 256, SMS>>>(sb1);
    cudaStreamWaitEvent(0, evWpp, 0);
    k_gate_mma<<<dim3(B_ / 128, FD_ / 64), 512, SMEM4>>>();
    k_final<<<B_ / 64, 256>>>(sg, sbe, Wh, bh, out);
}

// round 17
// speedup vs baseline: 1.0207x; 1.0207x over previous
#include <cuda_runtime.h>
#include <cuda_bf16.h>
#include <cstdint>
#include <cstddef>

#define B_  8192
#define F_  32
#define D_  128
#define H_  128
#define FD_ 4096
#define PADR 65
#define MPITCH 136   // bf16 pitch for 128-wide mma tiles (conflict-free)
#define PA 72        // bf16 pitch for 64-wide streaming-gemm tiles

// ---------------- scratch (device globals; no allocation) ----------------
__device__ float g_stacked[(size_t)B_ * FD_];
__device__ float g_t[(size_t)B_ * FD_];
__device__ float g_u1[F_ * H_];
__device__ float g_c1[F_ * H_];
__device__ float g_bgp[F_ * 2 * D_];
__device__ float g_bpp[2 * FD_];
__device__ float g_psum[(size_t)B_ * 64];
__device__ float g_psq [(size_t)B_ * 64];
__device__ __nv_bfloat16 g_WgpT_hi[(size_t)F_ * 2 * D_ * H_];
__device__ __nv_bfloat16 g_WgpT_lo[(size_t)F_ * 2 * D_ * H_];
__device__ __nv_bfloat16 g_g_hi[(size_t)B_ * H_];
__device__ __nv_bfloat16 g_g_lo[(size_t)B_ * H_];
__device__ __nv_bfloat16 g_WT_hi[(size_t)2 * FD_ * H_];
__device__ __nv_bfloat16 g_WT_lo[(size_t)2 * FD_ * H_];
__device__ __nv_bfloat16 g_sW2_hi[(size_t)H_ * FD_];
__device__ __nv_bfloat16 g_sW2_lo[(size_t)H_ * FD_];
__device__ __nv_bfloat16 g_sW1T_hi[(size_t)H_ * FD_];
__device__ __nv_bfloat16 g_sW1T_lo[(size_t)H_ * FD_];

// elu: single EX2 (abs err <= float eps at 1.0; expm1 path not needed at 1e-3 tol)
__device__ __forceinline__ float elu_f(float v) {
    return v > 0.f ? v : (__expf(v) - 1.f);
}
// sigmoid: single EX2 + FMA-pipe Newton reciprocal (no MUFU RCP).
// rel err ~1.3e-6; clamp keeps exp(-v) finite for extreme negative v.
__device__ __forceinline__ float sig_f(float v) {
    float e = __expf(fminf(-v, 87.f));
    float d = 1.f + e;
    float r = __uint_as_float(0x7EF311C3u - __float_as_uint(d));
    r = r * (2.f - d * r);
    r = r * (2.f - d * r);
    return r;
}
__device__ __forceinline__ void split2(float v, __nv_bfloat16& h, __nv_bfloat16& l) {
    h = __float2bfloat16(v);
    l = __float2bfloat16(v - __bfloat162float(h));
}
__device__ __forceinline__ void splitpack2(float v0, float v1, uint32_t& hp, uint32_t& lp) {
    __nv_bfloat16 h0, l0, h1, l1;
    split2(v0, h0, l0); split2(v1, h1, l1);
    __nv_bfloat162 hh; hh.x = h0; hh.y = h1;
    __nv_bfloat162 ll; ll.x = l0; ll.y = l1;
    hp = *(uint32_t*)&hh; lp = *(uint32_t*)&ll;
}

__device__ __forceinline__ void mma16816(float* c, const uint32_t* a, const uint32_t* b) {
    asm volatile("mma.sync.aligned.m16n8k16.row.col.f32.bf16.bf16.f32 "
        "{%0,%1,%2,%3}, {%4,%5,%6,%7}, {%8,%9}, {%0,%1,%2,%3};"
        : "+f"(c[0]), "+f"(c[1]), "+f"(c[2]), "+f"(c[3])
        : "r"(a[0]), "r"(a[1]), "r"(a[2]), "r"(a[3]), "r"(b[0]), "r"(b[1]));
}
__device__ __forceinline__ void ldsm4(uint32_t& r0, uint32_t& r1, uint32_t& r2,
                                      uint32_t& r3, uint32_t addr) {
    asm volatile("ldmatrix.sync.aligned.m8n8.x4.shared.b16 {%0,%1,%2,%3}, [%4];"
        : "=r"(r0), "=r"(r1), "=r"(r2), "=r"(r3) : "r"(addr));
}
__device__ __forceinline__ uint32_t smem_u32(const void* p) {
    uint32_t a;
    asm("{ .reg .u64 t; cvta.to.shared.u64 t, %1; cvt.u32.u64 %0, t; }" : "=r"(a) : "l"(p));
    return a;
}

// ---------------- K0: fold rank-1 + weight products (grid F x 4) ----------
__global__ void k_pre(const float* __restrict__ Wp,  const float* __restrict__ bp,
                      const float* __restrict__ fW1, const float* __restrict__ fb1,
                      const float* __restrict__ fW2, const float* __restrict__ fb2,
                      const float* __restrict__ fWg, const float* __restrict__ fbg)
{
    __shared__ float sA[128 * PADR];
    __shared__ float sB[16 * 128];
    const int f = blockIdx.x, q = blockIdx.y, tid = threadIdx.x;
    const int mh = q >> 1, nh = q & 1;

    if (q == 0) {
        float acc = 0.f;
        for (int d = 0; d < 128; d++)
            acc += fb2[f * D_ + d] * fWg[((size_t)f * D_ + d) * 256 + tid];
        g_bgp[f * 256 + tid] = acc + fbg[f * 256 + tid];
    } else if (q == 1 && tid < 128) {
        float acc = 0.f;
        for (int d = 0; d < 128; d++)
            acc += Wp[f * D_ + d] * fW1[((size_t)f * D_ + d) * H_ + tid];
        g_u1[f * H_ + tid] = acc;
    } else if (q == 2 && tid < 128) {
        float acc = 0.f;
        for (int d = 0; d < 128; d++)
            acc += bp[f * D_ + d] * fW1[((size_t)f * D_ + d) * H_ + tid];
        g_c1[f * H_ + tid] = acc + fb1[f * H_ + tid];
    }

    for (int i = tid; i < 128 * 64; i += 256) {
        int m = i >> 7, d = i & 127;
        sA[d * PADR + m] = fW2[((size_t)f * H_ + mh * 64 + m) * D_ + d];
    }
    __syncthreads();

    const int tx = tid & 15, ty = tid >> 4;
    float acc[4][8] = {};
    for (int k0 = 0; k0 < 128; k0 += 16) {
        __syncthreads();
        {
            int kk = tid >> 4, nb = (tid & 15) * 8;
            const float* src = fWg + ((size_t)f * D_ + k0 + kk) * 256 + nh * 128 + nb;
            float4 v0 = *(const float4*)src;
            float4 v1 = *(const float4*)(src + 4);
            *(float4*)(sB + kk * 128 + nb)     = v0;
            *(float4*)(sB + kk * 128 + nb + 4) = v1;
        }
        __syncthreads();
#pragma unroll
        for (int k = 0; k < 16; k++) {
            float av[4], bv[8];
#pragma unroll
            for (int i = 0; i < 4; i++) av[i] = sA[(k0 + k) * PADR + 4 * tx + i];
#pragma unroll
            for (int j = 0; j < 8; j++) bv[j] = sB[k * 128 + 8 * ty + j];
#pragma unroll
            for (int i = 0; i < 4; i++)
#pragma unroll
                for (int j = 0; j < 8; j++) acc[i][j] += av[i] * bv[j];
        }
    }
#pragma unroll
    for (int i = 0; i < 4; i++)
#pragma unroll
        for (int j = 0; j < 8; j++) {
            int m = mh * 64 + 4 * tx + i;
            int e = nh * 128 + 8 * ty + j;
            int p = (e < 128) ? (2 * e) : (2 * (e - 128) + 1);
            __nv_bfloat16 h, l; split2(acc[i][j], h, l);
            size_t idx = ((size_t)f * 256 + p) * H_ + m;
            g_WgpT_hi[idx] = h; g_WgpT_lo[idx] = l;
        }
}

// ---------------- K0b: pre-convert sW2 / sW1^T to bf16 hi/lo --------------
__global__ void k_conv(const float* __restrict__ sW1, const float* __restrict__ sW2)
{
    int i = blockIdx.x * 256 + threadIdx.x;
    {
        float v = sW2[i];
        __nv_bfloat16 h, l; split2(v, h, l);
        g_sW2_hi[i] = h; g_sW2_lo[i] = l;
    }
    {
        int hq = i >> 12, k = i & 4095;
        float v = sW1[(size_t)k * H_ + hq];
        __nv_bfloat16 h, l; split2(v, h, l);
        g_sW1T_hi[i] = h; g_sW1T_lo[i] = l;
    }
}

// ---------------- K1: per-feature GRN via mma (ldmatrix) + LN -------------
__global__ void __launch_bounds__(512, 1) k_grn2_mma(
    const float* __restrict__ x,  const float* __restrict__ Wp,
    const float* __restrict__ bp, const float* __restrict__ fg,
    const float* __restrict__ fbe)
{
    extern __shared__ char smg[];
    __nv_bfloat16* sAh = (__nv_bfloat16*)smg;
    __nv_bfloat16* sAl = sAh + 128 * MPITCH;
    __nv_bfloat16* sBh = sAl + 128 * MPITCH;
    __nv_bfloat16* sBl = sBh + 256 * MPITCH;
    float* s_val = (float*)smg;

    const int f = blockIdx.y, b0 = blockIdx.x * 128, tid = threadIdx.x;
    const int wid = tid >> 5, lane = tid & 31;

    {
        int r = tid >> 2, d0 = (tid & 3) * 32;
        float xv = x[(size_t)(b0 + r) * F_ + f];
        const float* u1 = g_u1 + f * H_ + d0;
        const float* c1 = g_c1 + f * H_ + d0;
#pragma unroll
        for (int j = 0; j < 16; j++) {
            float v0 = elu_f(xv * u1[2*j]   + c1[2*j]);
            float v1 = elu_f(xv * u1[2*j+1] + c1[2*j+1]);
            uint32_t hp, lp;
            splitpack2(v0, v1, hp, lp);
            *(uint32_t*)(sAh + r * MPITCH + d0 + 2*j) = hp;
            *(uint32_t*)(sAl + r * MPITCH + d0 + 2*j) = lp;
        }
    }
    {
        const uint4* srcH = (const uint4*)(g_WgpT_hi + (size_t)f * 256 * H_);
        const uint4* srcL = (const uint4*)(g_WgpT_lo + (size_t)f * 256 * H_);
        for (int i = tid; i < 256 * 16; i += 512) {
            int r = i >> 4, c = i & 15;
            *(uint4*)(sBh + r * MPITCH + c * 8) = srcH[r * 16 + c];
            *(uint4*)(sBl + r * MPITCH + c * 8) = srcL[r * 16 + c];
        }
    }
    __syncthreads();

    const int wm = (wid >> 3) * 64, wn = (wid & 7) * 32;
    const int lr = lane >> 2, lc = (lane & 3) * 2;
    const int g8 = lane >> 3, lr8 = lane & 7;
    const int arow = (g8 & 1) * 8 + lr8, acol = (g8 >> 1) * 8;
    const int brow = (g8 >> 1) * 8 + lr8, bcol = (g8 & 1) * 8;
    const uint32_t sbase = smem_u32(smg);

    float acc[4][4][4];
#pragma unroll
    for (int mt = 0; mt < 4; mt++)
#pragma unroll
        for (int nt = 0; nt < 4; nt++)
#pragma unroll
            for (int q = 0; q < 4; q++) acc[mt][nt][q] = 0.f;

#pragma unroll
    for (int pass = 0; pass < 3; pass++) {
        uint32_t uAr = sbase + ((pass == 1) ? 128u * MPITCH * 2u : 0u)
                     + (uint32_t)((wm + arow) * MPITCH + acol) * 2u;
        uint32_t uBr = sbase + 256u * MPITCH * 2u + ((pass == 2) ? 256u * MPITCH * 2u : 0u)
                     + (uint32_t)((wn + brow) * MPITCH + bcol) * 2u;
#pragma unroll
        for (int ks = 0; ks < 8; ks++) {
            const uint32_t k0b = ks * 32;
            uint32_t a[4][4], b[4][2];
#pragma unroll
            for (int mt = 0; mt < 4; mt++)
                ldsm4(a[mt][0], a[mt][1], a[mt][2], a[mt][3],
                      uAr + mt * (16 * MPITCH * 2) + k0b);
#pragma unroll
            for (int p = 0; p < 2; p++)
                ldsm4(b[2*p][0], b[2*p][1], b[2*p+1][0], b[2*p+1][1],
                      uBr + p * (16 * MPITCH * 2) + k0b);
#pragma unroll
            for (int mt = 0; mt < 4; mt++)
#pragma unroll
                for (int nt = 0; nt < 4; nt++)
                    mma16816(acc[mt][nt], a[mt], b[nt]);
        }
    }
    __syncthreads();

    const float* bgp = g_bgp + f * 256;
#pragma unroll
    for (int mt = 0; mt < 4; mt++) {
        int r0 = wm + mt * 16 + lr;
        float xv0 = x[(size_t)(b0 + r0) * F_ + f];
        float xv1 = x[(size_t)(b0 + r0 + 8) * F_ + f];
#pragma unroll
        for (int nt = 0; nt < 4; nt++) {
            int cc = wn + nt * 8 + lc;
            int j = cc >> 1;
            float ba = bgp[j], bs = bgp[128 + j];
            float wpj = Wp[f * D_ + j], bpj = bp[f * D_ + j];
            float a0 = acc[mt][nt][0] + ba, s0 = acc[mt][nt][1] + bs;
            s_val[r0 * 132 + j] = (xv0 * wpj + bpj) + a0 * sig_f(s0);
            float a1 = acc[mt][nt][2] + ba, s1 = acc[mt][nt][3] + bs;
            s_val[(r0 + 8) * 132 + j] = (xv1 * wpj + bpj) + a1 * sig_f(s1);
        }
    }
    __syncthreads();

    for (int rr = wid; rr < 128; rr += 16) {
        float v[4]; float sum = 0.f, sq = 0.f;
#pragma unroll
        for (int i = 0; i < 4; i++) {
            float val = s_val[rr * 132 + lane + 32 * i];
            v[i] = val; sum += val; sq += val * val;
        }
#pragma unroll
        for (int o = 16; o; o >>= 1) {
            sum += __shfl_xor_sync(0xffffffffu, sum, o);
            sq  += __shfl_xor_sync(0xffffffffu, sq,  o);
        }
        float mu  = sum * (1.f / 128.f);
        float var = sq  * (1.f / 128.f) - mu * mu;
        float rs  = rsqrtf(var + 1e-5f);
#pragma unroll
        for (int i = 0; i < 4; i++) {
            int d = lane + 32 * i;
            float o = (v[i] - mu) * rs * fg[f * D_ + d] + fbe[f * D_ + d];
            g_stacked[((size_t)(b0 + rr) * F_ + f) * D_ + d] = o;
        }
    }
}

// ---------------- K3: W'' = (sW2@sWg)^T via mma, streaming K=4096 ---------
__global__ void __launch_bounds__(256, 1) k_wpp_mma(const float* __restrict__ sWg,
                                                    const float* __restrict__ sb2,
                                                    const float* __restrict__ sbg)
{
    extern __shared__ char sm4[];
    const int ASZ = 64 * PA * 2, BSZ = 128 * PA * 2;
    __nv_bfloat16* Ahs[2] = {(__nv_bfloat16*)sm4, (__nv_bfloat16*)(sm4 + ASZ)};
    __nv_bfloat16* Als[2] = {(__nv_bfloat16*)(sm4 + 2*ASZ), (__nv_bfloat16*)(sm4 + 3*ASZ)};
    __nv_bfloat16* Bhs[2] = {(__nv_bfloat16*)(sm4 + 4*ASZ), (__nv_bfloat16*)(sm4 + 4*ASZ + BSZ)};
    __nv_bfloat16* Bls[2] = {(__nv_bfloat16*)(sm4 + 4*ASZ + 2*BSZ), (__nv_bfloat16*)(sm4 + 4*ASZ + 3*BSZ)};
    float* part = (float*)(sm4 + 4*ASZ + 4*BSZ);

    const int c0 = blockIdx.x * 64;
    const int tid = threadIdx.x, wid = tid >> 5, lane = tid & 31;
    const int kr = tid >> 2, cb = tid & 3;
    const int mr = tid >> 1, kh = (tid & 1) * 32;

    float areg[16];
    uint4 bregH[4], bregL[4];
    float baccp[16];
#pragma unroll
    for (int i = 0; i < 16; i++) baccp[i] = 0.f;

    auto ldchunk = [&](int ch) {
        const float* asrc = sWg + (size_t)(ch * 64 + kr) * (2 * FD_) + c0 + cb * 16;
#pragma unroll
        for (int j = 0; j < 4; j++) {
            float4 v = *(const float4*)(asrc + 4 * j);
            areg[4*j+0] = v.x; areg[4*j+1] = v.y; areg[4*j+2] = v.z; areg[4*j+3] = v.w;
        }
        const uint4* bh = (const uint4*)(g_sW2_hi + (size_t)mr * FD_ + ch * 64 + kh);
        const uint4* bl = (const uint4*)(g_sW2_lo + (size_t)mr * FD_ + ch * 64 + kh);
#pragma unroll
        for (int j = 0; j < 4; j++) { bregH[j] = bh[j]; bregL[j] = bl[j]; }
        float sv = sb2[ch * 64 + kr];
#pragma unroll
        for (int i = 0; i < 16; i++) baccp[i] += sv * areg[i];
    };
    auto stchunk = [&](int buf) {
        __nv_bfloat16* ah = Ahs[buf]; __nv_bfloat16* al = Als[buf];
#pragma unroll
        for (int i = 0; i < 16; i++) {
            int cl = cb * 16 + i;
            __nv_bfloat16 h, l; split2(areg[i], h, l);
            ah[cl * PA + kr] = h;
            al[cl * PA + kr] = l;
        }
        uint4* bh = (uint4*)(Bhs[buf] + mr * PA + kh);
        uint4* bl = (uint4*)(Bls[buf] + mr * PA + kh);
#pragma unroll
        for (int j = 0; j < 4; j++) { bh[j] = bregH[j]; bl[j] = bregL[j]; }
    };

    const int wc = (wid & 3) * 16, wm = (wid >> 2) * 64;
    const int lr = lane >> 2, lc = (lane & 3) * 2;
    float acc[8][4];
#pragma unroll
    for (int i = 0; i < 8; i++)
#pragma unroll
        for (int j = 0; j < 4; j++) acc[i][j] = 0.f;

    auto compute = [&](int buf) {
#pragma unroll
        for (int pass = 0; pass < 3; pass++) {
            const __nv_bfloat16* A = (pass == 1) ? Als[buf] : Ahs[buf];
            const __nv_bfloat16* B = (pass == 2) ? Bls[buf] : Bhs[buf];
#pragma unroll
            for (int ks = 0; ks < 4; ks++) {
                int k0 = ks * 16;
                uint32_t a[4];
                const __nv_bfloat16* ab = A + (wc + lr) * PA + k0 + lc;
                a[0] = *(const uint32_t*)ab;
                a[1] = *(const uint32_t*)(ab + 8 * PA);
                a[2] = *(const uint32_t*)(ab + 8);
                a[3] = *(const uint32_t*)(ab + 8 * PA + 8);
#pragma unroll
                for (int nt = 0; nt < 8; nt++) {
                    const __nv_bfloat16* bb = B + (wm + nt * 8 + lr) * PA + k0 + lc;
                    uint32_t b[2] = {*(const uint32_t*)bb, *(const uint32_t*)(bb + 8)};
                    mma16816(acc[nt], a, b);
                }
            }
        }
    };

    ldchunk(0); stchunk(0); __syncthreads();
    for (int ch = 0; ch < 64; ch++) {
        int cur = ch & 1;
        if (ch < 63) ldchunk(ch + 1);
        compute(cur);
        if (ch < 63) { stchunk(cur ^ 1); __syncthreads(); }
    }

#pragma unroll
    for (int nt = 0; nt < 8; nt++) {
        int m = wm + nt * 8 + lc;
#pragma unroll
        for (int half = 0; half < 2; half++) {
            int c = c0 + wc + lr + half * 8;
            int p = (c < FD_) ? (2 * c) : (2 * (c - FD_) + 1);
            uint32_t hp, lp;
            splitpack2(acc[nt][half * 2], acc[nt][half * 2 + 1], hp, lp);
            *(uint32_t*)(g_WT_hi + (size_t)p * H_ + m) = hp;
            *(uint32_t*)(g_WT_lo + (size_t)p * H_ + m) = lp;
        }
    }

    __syncthreads();
#pragma unroll
    for (int i = 0; i < 16; i++) part[tid * 16 + i] = baccp[i];
    __syncthreads();
    if (tid < 64) {
        int cb2 = tid >> 4, ii = tid & 15;
        float s = 0.f;
        for (int j = 0; j < 64; j++) s += part[(j * 4 + cb2) * 16 + ii];
        int c = c0 + tid;
        int p = (c < FD_) ? (2 * c) : (2 * (c - FD_) + 1);
        g_bpp[p] = s + sbg[c];
    }
}

// ---------------- K2: g = elu(flat @ sW1 + sb1) via mma -------------------
__global__ void __launch_bounds__(256, 1) k_sel1_mma(const float* __restrict__ sb1)
{
    extern __shared__ char sm5[];
    const int ASZ = 64 * PA * 2, BSZ = 128 * PA * 2;
    __nv_bfloat16* Ahs[2] = {(__nv_bfloat16*)sm5, (__nv_bfloat16*)(sm5 + ASZ)};
    __nv_bfloat16* Als[2] = {(__nv_bfloat16*)(sm5 + 2*ASZ), (__nv_bfloat16*)(sm5 + 3*ASZ)};
    __nv_bfloat16* Bhs[2] = {(__nv_bfloat16*)(sm5 + 4*ASZ), (__nv_bfloat16*)(sm5 + 4*ASZ + BSZ)};
    __nv_bfloat16* Bls[2] = {(__nv_bfloat16*)(sm5 + 4*ASZ + 2*BSZ), (__nv_bfloat16*)(sm5 + 4*ASZ + 3*BSZ)};

    const int b0 = blockIdx.x * 64;
    const int tid = threadIdx.x, wid = tid >> 5, lane = tid & 31;
    const int rr = tid >> 2, kq = (tid & 3) * 16;
    const int hr = tid >> 1, kh = (tid & 1) * 32;

    float areg[16];
    uint4 bregH[4], bregL[4];

    auto ldchunk = [&](int ch) {
        const float* asrc = g_stacked + (size_t)(b0 + rr) * FD_ + ch * 64 + kq;
#pragma unroll
        for (int j = 0; j < 4; j++) {
            float4 v = *(const float4*)(asrc + 4 * j);
            areg[4*j+0] = v.x; areg[4*j+1] = v.y; areg[4*j+2] = v.z; areg[4*j+3] = v.w;
        }
        const uint4* bh = (const uint4*)(g_sW1T_hi + (size_t)hr * FD_ + ch * 64 + kh);
        const uint4* bl = (const uint4*)(g_sW1T_lo + (size_t)hr * FD_ + ch * 64 + kh);
#pragma unroll
        for (int j = 0; j < 4; j++) { bregH[j] = bh[j]; bregL[j] = bl[j]; }
    };
    auto stchunk = [&](int buf) {
        __nv_bfloat16* ah = Ahs[buf]; __nv_bfloat16* al = Als[buf];
#pragma unroll
        for (int j = 0; j < 8; j++) {
            uint32_t hp, lp;
            splitpack2(areg[2*j], areg[2*j + 1], hp, lp);
            *(uint32_t*)(ah + rr * PA + kq + 2*j) = hp;
            *(uint32_t*)(al + rr * PA + kq + 2*j) = lp;
        }
        uint4* bh = (uint4*)(Bhs[buf] + hr * PA + kh);
        uint4* bl = (uint4*)(Bls[buf] + hr * PA + kh);
#pragma unroll
        for (int j = 0; j < 4; j++) { bh[j] = bregH[j]; bl[j] = bregL[j]; }
    };

    const int wc = (wid & 3) * 16, wm = (wid >> 2) * 64;
    const int lr = lane >> 2, lc = (lane & 3) * 2;
    float acc[8][4];
#pragma unroll
    for (int i = 0; i < 8; i++)
#pragma unroll
        for (int j = 0; j < 4; j++) acc[i][j] = 0.f;

    auto compute = [&](int buf) {
#pragma unroll
        for (int pass = 0; pass < 3; pass++) {
            const __nv_bfloat16* A = (pass == 1) ? Als[buf] : Ahs[buf];
            const __nv_bfloat16* B = (pass == 2) ? Bls[buf] : Bhs[buf];
#pragma unroll
            for (int ks = 0; ks < 4; ks++) {
                int k0 = ks * 16;
                uint32_t a[4];
                const __nv_bfloat16* ab = A + (wc + lr) * PA + k0 + lc;
                a[0] = *(const uint32_t*)ab;
                a[1] = *(const uint32_t*)(ab + 8 * PA);
                a[2] = *(const uint32_t*)(ab + 8);
                a[3] = *(const uint32_t*)(ab + 8 * PA + 8);
#pragma unroll
                for (int nt = 0; nt < 8; nt++) {
                    const __nv_bfloat16* bb = B + (wm + nt * 8 + lr) * PA + k0 + lc;
                    uint32_t b[2] = {*(const uint32_t*)bb, *(const uint32_t*)(bb + 8)};
                    mma16816(acc[nt], a, b);
                }
            }
        }
    };

    ldchunk(0); stchunk(0); __syncthreads();
    for (int ch = 0; ch < 64; ch++) {
        int cur = ch & 1;
        if (ch < 63) ldchunk(ch + 1);
        compute(cur);
        if (ch < 63) { stchunk(cur ^ 1); __syncthreads(); }
    }

#pragma unroll
    for (int nt = 0; nt < 8; nt++) {
        int h = wm + nt * 8 + lc;
        float bb0 = sb1[h], bb1 = sb1[h + 1];
#pragma unroll
        for (int half = 0; half < 2; half++) {
            int row = b0 + wc + lr + half * 8;
            float v0 = elu_f(acc[nt][half * 2]     + bb0);
            float v1 = elu_f(acc[nt][half * 2 + 1] + bb1);
            uint32_t hp, lp;
            splitpack2(v0, v1, hp, lp);
            *(uint32_t*)(g_g_hi + (size_t)row * H_ + h) = hp;
            *(uint32_t*)(g_g_lo + (size_t)row * H_ + h) = lp;
        }
    }
}

// ---------------- K4: gate mma (ldmatrix), emits LN partials --------------
__global__ void __launch_bounds__(512, 1) k_gate_mma()
{
    extern __shared__ __nv_bfloat16 smb[];
    __nv_bfloat16* sAh = smb;
    __nv_bfloat16* sAl = sAh + 128 * MPITCH;
    __nv_bfloat16* sBh = sAl + 128 * MPITCH;
    __nv_bfloat16* sBl = sBh + 128 * MPITCH;
    __shared__ float s_lns[128][4];
    __shared__ float s_lnq[128][4];

    const int m0 = blockIdx.x * 128;
    const int n0 = blockIdx.y * 128;
    const int tid = threadIdx.x;
    const int wid = tid >> 5, lane = tid & 31;

    for (int i = tid; i < 2048; i += 512) {
        int r = i >> 4, c = i & 15;
        *(uint4*)(sAh + r * MPITCH + c * 8) = *((const uint4*)(g_g_hi  + (size_t)(m0 + r) * H_) + c);
        *(uint4*)(sAl + r * MPITCH + c * 8) = *((const uint4*)(g_g_lo  + (size_t)(m0 + r) * H_) + c);
        *(uint4*)(sBh + r * MPITCH + c * 8) = *((const uint4*)(g_WT_hi + (size_t)(n0 + r) * H_) + c);
        *(uint4*)(sBl + r * MPITCH + c * 8) = *((const uint4*)(g_WT_lo + (size_t)(n0 + r) * H_) + c);
    }
    __syncthreads();

    const int wm = (wid & 3) * 32, wn = (wid >> 2) * 32;
    const int lr = lane >> 2, lc = (lane & 3) * 2;
    const int g8 = lane >> 3, lr8 = lane & 7;
    const int arow = (g8 & 1) * 8 + lr8, acol = (g8 >> 1) * 8;
    const int brow = (g8 >> 1) * 8 + lr8, bcol = (g8 & 1) * 8;
    const uint32_t sbase = smem_u32(smb);
    float acc[2][4][4] = {};

#pragma unroll
    for (int pass = 0; pass < 3; pass++) {
        uint32_t uAr = sbase + ((pass == 1) ? 128u * MPITCH * 2u : 0u)
                     + (uint32_t)((wm + arow) * MPITCH + acol) * 2u;
        uint32_t uBr = sbase + 256u * MPITCH * 2u + ((pass == 2) ? 128u * MPITCH * 2u : 0u)
                     + (uint32_t)((wn + brow) * MPITCH + bcol) * 2u;
#pragma unroll
        for (int ks = 0; ks < 8; ks++) {
            const uint32_t k0b = ks * 32;
            uint32_t a[2][4], b[4][2];
#pragma unroll
            for (int mt = 0; mt < 2; mt++)
                ldsm4(a[mt][0], a[mt][1], a[mt][2], a[mt][3],
                      uAr + mt * (16 * MPITCH * 2) + k0b);
#pragma unroll
            for (int p = 0; p < 2; p++)
                ldsm4(b[2*p][0], b[2*p][1], b[2*p+1][0], b[2*p+1][1],
                      uBr + p * (16 * MPITCH * 2) + k0b);
#pragma unroll
            for (int mt = 0; mt < 2; mt++)
#pragma unroll
                for (int nt = 0; nt < 4; nt++)
                    mma16816(acc[mt][nt], a[mt], b[nt]);
        }
    }

    float psum[4], psq[4];
#pragma unroll
    for (int i = 0; i < 4; i++) { psum[i] = 0.f; psq[i] = 0.f; }

#pragma unroll
    for (int mt = 0; mt < 2; mt++) {
        int r0 = m0 + wm + mt * 16 + lr;
#pragma unroll
        for (int nt = 0; nt < 4; nt++) {
            int cc = n0 + wn + nt * 8 + lc;
            int j = cc >> 1;
            float ba = g_bpp[cc], bs = g_bpp[cc + 1];
            float a0 = acc[mt][nt][0] + ba, s0 = acc[mt][nt][1] + bs;
            float t0 = g_stacked[(size_t)r0 * FD_ + j] + a0 * sig_f(s0);
            g_t[(size_t)r0 * FD_ + j] = t0;
            psum[mt*2] += t0; psq[mt*2] += t0 * t0;
            float a1 = acc[mt][nt][2] + ba, s1 = acc[mt][nt][3] + bs;
            float t1 = g_stacked[(size_t)(r0 + 8) * FD_ + j] + a1 * sig_f(s1);
            g_t[(size_t)(r0 + 8) * FD_ + j] = t1;
            psum[mt*2+1] += t1; psq[mt*2+1] += t1 * t1;
        }
    }

#pragma unroll
    for (int o = 1; o < 4; o <<= 1) {
#pragma unroll
        for (int i = 0; i < 4; i++) {
            psum[i] += __shfl_xor_sync(0xffffffffu, psum[i], o);
            psq[i]  += __shfl_xor_sync(0xffffffffu, psq[i],  o);
        }
    }
    if ((lane & 3) == 0) {
#pragma unroll
        for (int mt = 0; mt < 2; mt++) {
#pragma unroll
            for (int half = 0; half < 2; half++) {
                int rl = wm + mt * 16 + lr + half * 8;
                s_lns[rl][wid >> 2] = psum[mt*2 + half];
                s_lnq[rl][wid >> 2] = psq[mt*2 + half];
            }
        }
    }
    __syncthreads();
    if (tid < 128) {
        float s = s_lns[tid][0] + s_lns[tid][1] + s_lns[tid][2] + s_lns[tid][3];
        float q = s_lnq[tid][0] + s_lnq[tid][1] + s_lnq[tid][2] + s_lnq[tid][3];
        g_psum[(size_t)(m0 + tid) * 64 + blockIdx.y] = s;
        g_psq [(size_t)(m0 + tid) * 64 + blockIdx.y] = q;
    }
}

// ---------------- K5: LN(4096) -> logits GEMM -> softmax -> select --------
__global__ void k_final(const float* __restrict__ sg, const float* __restrict__ sbe,
                        const float* __restrict__ Wh, const float* __restrict__ bh,
                        float* __restrict__ out)
{
    __shared__ float As[2][32 * PADR];
    __shared__ float Bs[2][32 * 32];
    __shared__ float smu[64], srs[64];
    __shared__ float L[64 * 33];
    const int m0  = blockIdx.x * 64;
    const int tid = threadIdx.x;
    const int w = tid >> 5, l = tid & 31;

    for (int rr = w; rr < 64; rr += 8) {
        size_t base = (size_t)(m0 + rr) * 64;
        float sum = g_psum[base + l] + g_psum[base + 32 + l];
        float sq  = g_psq [base + l] + g_psq [base + 32 + l];
#pragma unroll
        for (int o = 16; o; o >>= 1) {
            sum += __shfl_xor_sync(0xffffffffu, sum, o);
            sq  += __shfl_xor_sync(0xffffffffu, sq,  o);
        }
        if (l == 0) {
            float mu  = sum * (1.f / 4096.f);
            float var = sq  * (1.f / 4096.f) - mu * mu;
            smu[rr] = mu;
            srs[rr] = rsqrtf(var + 1e-5f);
        }
    }
    __syncthreads();

    const int tx = tid & 15, ty = tid >> 4;
    const int ar = tid >> 2, akq = (tid & 3) * 8;
    const int bkk = tid >> 3, bnb = (tid & 7) * 4;
    float areg[8], sgr[8], sber[8];
    float4 breg;
    float mu_r = 0.f, rs_r = 0.f;

    auto ldchunk = [&](int ch) {
        const float* src = g_t + (size_t)(m0 + ar) * FD_ + ch * 32 + akq;
        float4 v0 = *(const float4*)src;
        float4 v1 = *(const float4*)(src + 4);
        areg[0] = v0.x; areg[1] = v0.y; areg[2] = v0.z; areg[3] = v0.w;
        areg[4] = v1.x; areg[5] = v1.y; areg[6] = v1.z; areg[7] = v1.w;
        float4 s0 = *(const float4*)(sg  + ch * 32 + akq);
        float4 s1 = *(const float4*)(sg  + ch * 32 + akq + 4);
        float4 e0 = *(const float4*)(sbe + ch * 32 + akq);
        float4 e1 = *(const float4*)(sbe + ch * 32 + akq + 4);
        sgr[0]=s0.x; sgr[1]=s0.y; sgr[2]=s0.z; sgr[3]=s0.w;
        sgr[4]=s1.x; sgr[5]=s1.y; sgr[6]=s1.z; sgr[7]=s1.w;
        sber[0]=e0.x; sber[1]=e0.y; sber[2]=e0.z; sber[3]=e0.w;
        sber[4]=e1.x; sber[5]=e1.y; sber[6]=e1.z; sber[7]=e1.w;
        breg = *(const float4*)(Wh + (size_t)(ch * 32 + bkk) * F_ + bnb);
    };
    auto stchunk = [&](int buf) {
#pragma unroll
        for (int q = 0; q < 8; q++)
            As[buf][(akq + q) * PADR + ar] = (areg[q] - mu_r) * rs_r * sgr[q] + sber[q];
        *(float4*)(Bs[buf] + bkk * 32 + bnb) = breg;
    };

    mu_r = smu[ar]; rs_r = srs[ar];
    float acc[4][2] = {};

    ldchunk(0); stchunk(0); __syncthreads();
    for (int ch = 0; ch < 128; ch++) {
        int cur = ch & 1;
        if (ch < 127) ldchunk(ch + 1);
        {
            const float* Ac = As[cur];
            const float* Bc = Bs[cur];
#pragma unroll
            for (int k = 0; k < 32; k++) {
                float a0 = Ac[k * PADR + 4 * tx + 0];
                float a1 = Ac[k * PADR + 4 * tx + 1];
                float a2 = Ac[k * PADR + 4 * tx + 2];
                float a3 = Ac[k * PADR + 4 * tx + 3];
                float b0 = Bc[k * 32 + 2 * ty];
                float b1 = Bc[k * 32 + 2 * ty + 1];
                acc[0][0] += a0 * b0; acc[0][1] += a0 * b1;
                acc[1][0] += a1 * b0; acc[1][1] += a1 * b1;
                acc[2][0] += a2 * b0; acc[2][1] += a2 * b1;
                acc[3][0] += a3 * b0; acc[3][1] += a3 * b1;
            }
        }
        if (ch < 127) { stchunk(cur ^ 1); __syncthreads(); }
    }
    __syncthreads();
#pragma unroll
    for (int i = 0; i < 4; i++)
#pragma unroll
        for (int j = 0; j < 2; j++)
            L[(4 * tx + i) * 33 + 2 * ty + j] = acc[i][j] + bh[2 * ty + j];
    __syncthreads();

    for (int rr = w; rr < 64; rr += 8) {
        int b = m0 + rr;
        float logit = L[rr * 33 + l];
        float mx = logit;
#pragma unroll
        for (int o = 16; o; o >>= 1) mx = fmaxf(mx, __shfl_xor_sync(0xffffffffu, mx, o));
        float e = __expf(logit - mx);
        float s = e;
#pragma unroll
        for (int o = 16; o; o >>= 1) s += __shfl_xor_sync(0xffffffffu, s, o);
        float wt = e / s;
        out[(size_t)B_ * D_ + (size_t)b * F_ + l] = wt;

        float accd[4] = {0.f, 0.f, 0.f, 0.f};
        const float* srow = g_stacked + (size_t)b * FD_;
        for (int ff = 0; ff < 32; ff++) {
            float wf = __shfl_sync(0xffffffffu, wt, ff);
#pragma unroll
            for (int i = 0; i < 4; i++)
                accd[i] += srow[ff * 128 + l + 32 * i] * wf;
        }
#pragma unroll
        for (int i = 0; i < 4; i++)
            out[(size_t)b * D_ + l + 32 * i] = accd[i];
    }
}

// ---------------- launch (two-stream overlap, capture-safe fork) ----------
extern "C" void kernel_launch(void* const* d_in, const int* in_sizes, int n_in,
                              void* d_out, int out_size)
{
    const float* x   = (const float*)d_in[0];
    const float* Wp  = (const float*)d_in[1];
    const float* bp  = (const float*)d_in[2];
    const float* fW1 = (const float*)d_in[3];
    const float* fb1 = (const float*)d_in[4];
    const float* fW2 = (const float*)d_in[5];
    const float* fb2 = (const float*)d_in[6];
    const float* fWg = (const float*)d_in[7];
    const float* fbg = (const float*)d_in[8];
    const float* fg  = (const float*)d_in[9];
    const float* fbe = (const float*)d_in[10];
    const float* sW1 = (const float*)d_in[11];
    const float* sb1 = (const float*)d_in[12];
    const float* sW2 = (const float*)d_in[13];
    const float* sb2 = (const float*)d_in[14];
    const float* sWg = (const float*)d_in[15];
    const float* sbg = (const float*)d_in[16];
    const float* sg  = (const float*)d_in[17];
    const float* sbe = (const float*)d_in[18];
    const float* Wh  = (const float*)d_in[19];
    const float* bh  = (const float*)d_in[20];
    float* out = (float*)d_out;

    const int ASZ = 64 * PA * 2, BSZ = 128 * PA * 2;
    const int SMG   = (2 * 128 + 2 * 256) * MPITCH * (int)sizeof(__nv_bfloat16); // 208896
    const int SMEM4 = 4 * 128 * MPITCH * (int)sizeof(__nv_bfloat16);             // 139264
    const int SMW   = 4 * ASZ + 4 * BSZ + 256 * 16 * (int)sizeof(float);
    const int SMS   = 4 * ASZ + 4 * BSZ;

    static cudaStream_t s1 = nullptr;
    static cudaEvent_t evRoot = nullptr, evConv = nullptr, evWpp = nullptr;
    if (!s1) {
        cudaFuncSetAttribute(k_grn2_mma, cudaFuncAttributeMaxDynamicSharedMemorySize, SMG);
        cudaFuncSetAttribute(k_gate_mma, cudaFuncAttributeMaxDynamicSharedMemorySize, SMEM4);
        cudaFuncSetAttribute(k_wpp_mma,  cudaFuncAttributeMaxDynamicSharedMemorySize, SMW);
        cudaFuncSetAttribute(k_sel1_mma, cudaFuncAttributeMaxDynamicSharedMemorySize, SMS);
        cudaStreamCreateWithFlags(&s1, cudaStreamNonBlocking);
        cudaEventCreateWithFlags(&evRoot, cudaEventDisableTiming);
        cudaEventCreateWithFlags(&evConv, cudaEventDisableTiming);
        cudaEventCreateWithFlags(&evWpp,  cudaEventDisableTiming);
    }

    // fork: conv + wpp chain on s1 (hidden under pre/grn2)
    cudaEventRecord(evRoot, 0);
    cudaStreamWaitEvent(s1, evRoot, 0);
    k_conv<<<2048, 256, 0, s1>>>(sW1, sW2);
    cudaEventRecord(evConv, s1);
    k_wpp_mma<<<2 * FD_ / 64, 256, SMW, s1>>>(sWg, sb2, sbg);
    cudaEventRecord(evWpp, s1);

    // main chain
    k_pre<<<dim3(F_, 4), 256>>>(Wp, bp, fW1, fb1, fW2, fb2, fWg, fbg);
    k_grn2_mma<<<dim3(B_ / 128, F_), 512, SMG>>>(x, Wp, bp, fg, fbe);
    cudaStreamWaitEvent(0, evConv, 0);
    k_sel1_mma<<<B_ / 64, 256, SMS>>>(sb1);
    cudaStreamWaitEvent(0, evWpp, 0);
    k_gate_mma<<<dim3(B_ / 128, FD_ / 64), 512, SMEM4>>>();
    k_final<<<B_ / 64, 256>>>(sg, sbe, Wh, bh, out);
}